// round 1
// baseline (speedup 1.0000x reference)
#include <cuda_runtime.h>
#include <math.h>

// Problem dims (fixed shapes)
#define B_DIM 2048
#define S_DIM 32
#define C_DIM 1280
#define H_DIM 8
#define D_DIM 160
#define M_TOT (B_DIM * S_DIM)   // 65536 tokens
#define K_DIM C_DIM              // 1280

// ---------------- scratch (static device allocations; no cudaMalloc) ----------------
__device__ float g_qkv[(size_t)3 * M_TOT * C_DIM];   // [proj][token][C]  ~1.0 GB
__device__ float g_attn[(size_t)M_TOT * C_DIM];      // [token][C]        ~335 MB
__device__ float g_pe[S_DIM * C_DIM];                // positional embedding table

// ---------------- helpers ----------------
__device__ __forceinline__ float to_tf32(float x) {
    unsigned u;
    asm("cvt.rna.tf32.f32 %0, %1;" : "=r"(u) : "f"(x));
    return __uint_as_float(u);
}

__device__ __forceinline__ void mma_tf32(float* d, const unsigned* a, unsigned b0, unsigned b1) {
    asm volatile(
        "mma.sync.aligned.m16n8k8.row.col.f32.tf32.tf32.f32 "
        "{%0,%1,%2,%3}, {%4,%5,%6,%7}, {%8,%9}, {%0,%1,%2,%3};\n"
        : "+f"(d[0]), "+f"(d[1]), "+f"(d[2]), "+f"(d[3])
        : "r"(a[0]), "r"(a[1]), "r"(a[2]), "r"(a[3]), "r"(b0), "r"(b1));
}

// ---------------- positional embedding table ----------------
__global__ void pe_kernel() {
    int idx = blockIdx.x * blockDim.x + threadIdx.x;
    if (idx >= S_DIM * C_DIM) return;
    int s = idx / C_DIM;
    int c = idx % C_DIM;
    int j = c >> 1;
    // div = exp(2j * (-ln(10000)/C))
    float f = expf((float)(2 * j) * (-9.210340371976184f / (float)C_DIM));
    float ang = (float)s * f;
    g_pe[idx] = (c & 1) ? cosf(ang) : sinf(ang);
}

// ---------------- tf32 GEMM: C[m,n] = sum_k A[m,k] * W[n,k]  (+pe on A, +bias) ----------------
// BM=128, BN=128, BK=16, 256 threads (8 warps: 4 along M x 2 along N; warp tile 32x64)
constexpr int BM = 128, BN = 128, BK = 16;
constexpr int ASTR = BK + 1;  // smem padding

template <bool QKV>
__global__ __launch_bounds__(256) void gemm_tf32_kernel(
    const float* __restrict__ A_in,   // QKV: hidden_states ; OUT: unused (uses g_attn)
    const float* __restrict__ W0,
    const float* __restrict__ W1,
    const float* __restrict__ W2,
    const float* __restrict__ bias,   // OUT only
    float* __restrict__ C_out)        // OUT: d_out ; QKV: unused (uses g_qkv)
{
    __shared__ float As[BM * ASTR];
    __shared__ float Bs[BN * ASTR];

    const int bx = blockIdx.x, by = blockIdx.y;
    int proj, ncol0;
    const float* W;
    float* Cp;
    if (QKV) {
        proj = bx / 10;           // 30 n-tiles: 10 per projection
        ncol0 = (bx % 10) * BN;
        W = (proj == 0) ? W0 : (proj == 1) ? W1 : W2;
        Cp = g_qkv + (size_t)proj * M_TOT * C_DIM;
    } else {
        proj = 0;
        ncol0 = bx * BN;
        W = W0;
        Cp = C_out;
    }
    const float* A = QKV ? A_in : g_attn;

    const int m0 = by * BM;
    const int tid = threadIdx.x;
    const int warp = tid >> 5, lane = tid & 31;
    const int wm = (warp & 3) * 32;   // warp M offset
    const int wn = (warp >> 2) * 64;  // warp N offset
    const int g = lane >> 2, tg = lane & 3;

    float acc[2][8][4];
#pragma unroll
    for (int mi = 0; mi < 2; mi++)
#pragma unroll
        for (int ni = 0; ni < 8; ni++)
#pragma unroll
            for (int r = 0; r < 4; r++) acc[mi][ni][r] = 0.0f;

    // global load mapping: thread -> (row = tid/4 [+64], 4 floats at col (tid%4)*4)
    const int lr = tid >> 2;
    const int lc = (tid & 3) * 4;
    const float* Aptr = A + (size_t)(m0 + lr) * K_DIM + lc;
    const float* Wptr = W + (size_t)(ncol0 + lr) * K_DIM + lc;

    float4 ra[2], rb[2], rp[2];
    // prefetch k-tile 0
#pragma unroll
    for (int rr = 0; rr < 2; rr++) {
        ra[rr] = *(const float4*)(Aptr + (size_t)rr * 64 * K_DIM);
        rb[rr] = *(const float4*)(Wptr + (size_t)rr * 64 * K_DIM);
        if (QKV) {
            int s = (m0 + lr + rr * 64) & (S_DIM - 1);
            rp[rr] = *(const float4*)(g_pe + s * C_DIM + lc);
        }
    }

    const int NT = K_DIM / BK;  // 80
    for (int kt = 0; kt < NT; kt++) {
        // store prefetched tile to smem (tf32-rounded)
#pragma unroll
        for (int rr = 0; rr < 2; rr++) {
            int row = lr + rr * 64;
            float4 a = ra[rr];
            if (QKV) { a.x += rp[rr].x; a.y += rp[rr].y; a.z += rp[rr].z; a.w += rp[rr].w; }
            As[row * ASTR + lc + 0] = to_tf32(a.x);
            As[row * ASTR + lc + 1] = to_tf32(a.y);
            As[row * ASTR + lc + 2] = to_tf32(a.z);
            As[row * ASTR + lc + 3] = to_tf32(a.w);
            float4 w = rb[rr];
            Bs[row * ASTR + lc + 0] = to_tf32(w.x);
            Bs[row * ASTR + lc + 1] = to_tf32(w.y);
            Bs[row * ASTR + lc + 2] = to_tf32(w.z);
            Bs[row * ASTR + lc + 3] = to_tf32(w.w);
        }
        __syncthreads();

        if (kt + 1 < NT) {
            int k0 = (kt + 1) * BK;
#pragma unroll
            for (int rr = 0; rr < 2; rr++) {
                ra[rr] = *(const float4*)(Aptr + (size_t)rr * 64 * K_DIM + k0);
                rb[rr] = *(const float4*)(Wptr + (size_t)rr * 64 * K_DIM + k0);
                if (QKV) {
                    int s = (m0 + lr + rr * 64) & (S_DIM - 1);
                    rp[rr] = *(const float4*)(g_pe + s * C_DIM + k0 + lc);
                }
            }
        }

        // compute: 2 k-steps of m16n8k8
#pragma unroll
        for (int ks = 0; ks < BK / 8; ks++) {
            unsigned af[2][4];
#pragma unroll
            for (int mi = 0; mi < 2; mi++) {
                int ar = wm + mi * 16;
                af[mi][0] = __float_as_uint(As[(ar + g) * ASTR + ks * 8 + tg]);
                af[mi][1] = __float_as_uint(As[(ar + g + 8) * ASTR + ks * 8 + tg]);
                af[mi][2] = __float_as_uint(As[(ar + g) * ASTR + ks * 8 + tg + 4]);
                af[mi][3] = __float_as_uint(As[(ar + g + 8) * ASTR + ks * 8 + tg + 4]);
            }
#pragma unroll
            for (int ni = 0; ni < 8; ni++) {
                int bc = wn + ni * 8;
                unsigned b0 = __float_as_uint(Bs[(bc + g) * ASTR + ks * 8 + tg]);
                unsigned b1 = __float_as_uint(Bs[(bc + g) * ASTR + ks * 8 + tg + 4]);
#pragma unroll
                for (int mi = 0; mi < 2; mi++) mma_tf32(acc[mi][ni], af[mi], b0, b1);
            }
        }
        __syncthreads();
    }

    // epilogue
#pragma unroll
    for (int mi = 0; mi < 2; mi++) {
#pragma unroll
        for (int ni = 0; ni < 8; ni++) {
            int row = m0 + wm + mi * 16 + g;
            int col = ncol0 + wn + ni * 8 + tg * 2;
            float b0v = 0.0f, b1v = 0.0f;
            if (!QKV) { b0v = bias[col]; b1v = bias[col + 1]; }
            float2 v01 = make_float2(acc[mi][ni][0] + b0v, acc[mi][ni][1] + b1v);
            float2 v23 = make_float2(acc[mi][ni][2] + b0v, acc[mi][ni][3] + b1v);
            *(float2*)(Cp + (size_t)row * C_DIM + col) = v01;
            *(float2*)(Cp + (size_t)(row + 8) * C_DIM + col) = v23;
        }
    }
}

// ---------------- attention: one CTA per (b, h) ----------------
// smem: q,k,v as [32][164] floats (stride 164 -> conflict-free float4 access)
constexpr int KSTR = 164;                       // floats per row (160 used)
constexpr int ATTN_SMEM = 3 * 32 * KSTR * 4;    // bytes = 62976

__global__ __launch_bounds__(256) void attn_kernel() {
    extern __shared__ float sm[];
    float* qs = sm;
    float* ks = sm + 32 * KSTR;
    float* vs = sm + 2 * 32 * KSTR;

    const int h = blockIdx.x;
    const int b = blockIdx.y;
    const int tid = threadIdx.x;
    const size_t base = (size_t)(b * S_DIM) * C_DIM + h * D_DIM;

    // load q,k,v tiles: 3 * 32 rows * 40 float4
    for (int t = tid; t < 3 * 32 * 40; t += 256) {
        int arr = t / 1280;
        int r = t - arr * 1280;
        int i = r / 40;
        int c4 = r - i * 40;
        float4 val = *(const float4*)(g_qkv + (size_t)arr * M_TOT * C_DIM + base +
                                      (size_t)i * C_DIM + c4 * 4);
        *(float4*)(sm + arr * (32 * KSTR) + i * KSTR + c4 * 4) = val;
    }
    __syncthreads();

    const int warp = tid >> 5, lane = tid & 31;
    const int i0 = warp * 4;

    // scores: warp handles rows i0..i0+3; lane = key index j
    float s0 = 0.f, s1 = 0.f, s2 = 0.f, s3 = 0.f;
    const float4* k4 = (const float4*)(ks + lane * KSTR);
    const float4* q0 = (const float4*)(qs + (i0 + 0) * KSTR);
    const float4* q1 = (const float4*)(qs + (i0 + 1) * KSTR);
    const float4* q2 = (const float4*)(qs + (i0 + 2) * KSTR);
    const float4* q3 = (const float4*)(qs + (i0 + 3) * KSTR);
#pragma unroll
    for (int c = 0; c < 40; c++) {
        float4 kv = k4[c];
        float4 a0 = q0[c], a1 = q1[c], a2 = q2[c], a3 = q3[c];
        s0 += a0.x * kv.x + a0.y * kv.y + a0.z * kv.z + a0.w * kv.w;
        s1 += a1.x * kv.x + a1.y * kv.y + a1.z * kv.z + a1.w * kv.w;
        s2 += a2.x * kv.x + a2.y * kv.y + a2.z * kv.z + a2.w * kv.w;
        s3 += a3.x * kv.x + a3.y * kv.y + a3.z * kv.z + a3.w * kv.w;
    }

    const float SCALE = 0.07905694150420949f;  // 1/sqrt(160)
    const unsigned FULL = 0xFFFFFFFFu;
    float p[4];
    float sv[4] = {s0 * SCALE, s1 * SCALE, s2 * SCALE, s3 * SCALE};
#pragma unroll
    for (int ii = 0; ii < 4; ii++) {
        float m = sv[ii];
#pragma unroll
        for (int o = 16; o > 0; o >>= 1) m = fmaxf(m, __shfl_xor_sync(FULL, m, o));
        float e = expf(sv[ii] - m);
        float sum = e;
#pragma unroll
        for (int o = 16; o > 0; o >>= 1) sum += __shfl_xor_sync(FULL, sum, o);
        p[ii] = e / sum;   // lane holds p[i0+ii][lane]
    }

    // out = P @ V : lane owns float4 chunk 'lane' (+ chunk lane+32 for lane<8)
    float4 oa[4], ob[4];
#pragma unroll
    for (int ii = 0; ii < 4; ii++) {
        oa[ii] = make_float4(0.f, 0.f, 0.f, 0.f);
        ob[ii] = make_float4(0.f, 0.f, 0.f, 0.f);
    }
    const bool has2 = (lane < 8);
#pragma unroll
    for (int j = 0; j < 32; j++) {
        const float4* v4 = (const float4*)(vs + j * KSTR);
        float4 vb = v4[lane];
        float4 vb2 = v4[has2 ? (lane + 32) : lane];
        float pj0 = __shfl_sync(FULL, p[0], j);
        float pj1 = __shfl_sync(FULL, p[1], j);
        float pj2 = __shfl_sync(FULL, p[2], j);
        float pj3 = __shfl_sync(FULL, p[3], j);
        oa[0].x += pj0 * vb.x; oa[0].y += pj0 * vb.y; oa[0].z += pj0 * vb.z; oa[0].w += pj0 * vb.w;
        oa[1].x += pj1 * vb.x; oa[1].y += pj1 * vb.y; oa[1].z += pj1 * vb.z; oa[1].w += pj1 * vb.w;
        oa[2].x += pj2 * vb.x; oa[2].y += pj2 * vb.y; oa[2].z += pj2 * vb.z; oa[2].w += pj2 * vb.w;
        oa[3].x += pj3 * vb.x; oa[3].y += pj3 * vb.y; oa[3].z += pj3 * vb.z; oa[3].w += pj3 * vb.w;
        ob[0].x += pj0 * vb2.x; ob[0].y += pj0 * vb2.y; ob[0].z += pj0 * vb2.z; ob[0].w += pj0 * vb2.w;
        ob[1].x += pj1 * vb2.x; ob[1].y += pj1 * vb2.y; ob[1].z += pj1 * vb2.z; ob[1].w += pj1 * vb2.w;
        ob[2].x += pj2 * vb2.x; ob[2].y += pj2 * vb2.y; ob[2].z += pj2 * vb2.z; ob[2].w += pj2 * vb2.w;
        ob[3].x += pj3 * vb2.x; ob[3].y += pj3 * vb2.y; ob[3].z += pj3 * vb2.z; ob[3].w += pj3 * vb2.w;
    }
#pragma unroll
    for (int ii = 0; ii < 4; ii++) {
        float* orow = g_attn + base + (size_t)(i0 + ii) * C_DIM;
        *(float4*)(orow + lane * 4) = oa[ii];
        if (has2) *(float4*)(orow + 128 + lane * 4) = ob[ii];
    }
}

// ---------------- launch ----------------
extern "C" void kernel_launch(void* const* d_in, const int* in_sizes, int n_in,
                              void* d_out, int out_size) {
    (void)in_sizes; (void)n_in; (void)out_size;
    const float* hidden = (const float*)d_in[0];
    const float* Wq = (const float*)d_in[1];
    const float* Wk = (const float*)d_in[2];
    const float* Wv = (const float*)d_in[3];
    const float* Wo = (const float*)d_in[4];
    const float* bo = (const float*)d_in[5];
    float* out = (float*)d_out;

    cudaFuncSetAttribute(attn_kernel, cudaFuncAttributeMaxDynamicSharedMemorySize, ATTN_SMEM);

    // 1) positional embedding table
    pe_kernel<<<(S_DIM * C_DIM + 255) / 256, 256>>>();

    // 2) fused QKV projection (pos-embed added on the fly)
    gemm_tf32_kernel<true><<<dim3(30, M_TOT / BM), 256>>>(hidden, Wq, Wk, Wv, nullptr, nullptr);

    // 3) attention per (b, h)
    attn_kernel<<<dim3(H_DIM, B_DIM), 256, ATTN_SMEM>>>();

    // 4) output projection + bias
    gemm_tf32_kernel<false><<<dim3(C_DIM / BN, M_TOT / BM), 256>>>(nullptr, Wo, nullptr, nullptr, bo, out);
}

// round 8
// speedup vs baseline: 1.2822x; 1.2822x over previous
#include <cuda_runtime.h>
#include <math.h>
#include <stdint.h>

// Problem dims (fixed shapes)
#define B_DIM 2048
#define S_DIM 32
#define C_DIM 1280
#define H_DIM 8
#define D_DIM 160
#define M_TOT (B_DIM * S_DIM)   // 65536 tokens
#define K_DIM C_DIM

// ---------------- scratch (static device globals; no cudaMalloc) ----------------
__device__ float g_qkv[(size_t)3 * M_TOT * C_DIM];   // [proj][token][C]
__device__ float g_attn[(size_t)M_TOT * C_DIM];      // attention output
__device__ float g_pe[S_DIM * C_DIM];                // positional embedding

// ---------------- helpers ----------------
__device__ __forceinline__ float to_tf32(float x) {
    unsigned u;
    asm("cvt.rna.tf32.f32 %0, %1;" : "=r"(u) : "f"(x));
    return __uint_as_float(u);
}
__device__ __forceinline__ void mma_tf32(float* d, unsigned a0, unsigned a1, unsigned a2,
                                         unsigned a3, unsigned b0, unsigned b1) {
    asm volatile(
        "mma.sync.aligned.m16n8k8.row.col.f32.tf32.tf32.f32 "
        "{%0,%1,%2,%3}, {%4,%5,%6,%7}, {%8,%9}, {%0,%1,%2,%3};\n"
        : "+f"(d[0]), "+f"(d[1]), "+f"(d[2]), "+f"(d[3])
        : "r"(a0), "r"(a1), "r"(a2), "r"(a3), "r"(b0), "r"(b1));
}
#define F2U(x) __float_as_uint(x)

// ---------------- positional embedding table ----------------
__global__ void pe_kernel() {
    int idx = blockIdx.x * blockDim.x + threadIdx.x;
    if (idx >= S_DIM * C_DIM) return;
    int s = idx / C_DIM;
    int c = idx % C_DIM;
    int j = c >> 1;
    float f = expf((float)(2 * j) * (-9.210340371976184f / (float)C_DIM));
    float ang = (float)s * f;
    g_pe[idx] = (c & 1) ? cosf(ang) : sinf(ang);
}

// ---------------- tf32 GEMM: C[m,n] = sum_k A[m,k] * W[n,k]  (+pe on A, +bias) ----------------
// Block 128x256, BK=16, 256 threads, 8 warps (2 along M x 4 along N), warp tile 64x64.
// Smem layout permuted for vectorized fragment loads:
//   element (row,k) stored at  row*16 + ((k&3)^(row&3))*4 + (k>>2)
// so a thread's 4 needed values {tg, tg+4, tg+8, tg+12} are one contiguous float4.
constexpr int BM = 128, BN = 256, BK = 16;
constexpr int NT = K_DIM / BK;   // 80

template <bool QKV>
__global__ __launch_bounds__(256) void gemm_tf32_kernel(
    const float* __restrict__ A_in,   // QKV: hidden ; OUT: unused (uses g_attn)
    const float* __restrict__ W0,
    const float* __restrict__ W1,
    const float* __restrict__ W2,
    const float* __restrict__ bias,   // OUT only
    float* __restrict__ C_out)        // OUT: d_out ; QKV: unused (uses g_qkv)
{
    __shared__ float As[2][BM * 16];  // 16 KB
    __shared__ float Bs[2][BN * 16];  // 32 KB   (total 48 KB)

    int proj, ncol;
    const float* W;
    float* Cp;
    if (QKV) {
        proj = blockIdx.x / 5;
        ncol = (blockIdx.x % 5) * BN;
        W = (proj == 0) ? W0 : (proj == 1) ? W1 : W2;
        Cp = g_qkv + (size_t)proj * M_TOT * C_DIM;
    } else {
        ncol = blockIdx.x * BN;
        W = W0;
        Cp = C_out;
    }
    const float* A = QKV ? A_in : g_attn;
    const int m0 = blockIdx.y * BM;

    const int tid = threadIdx.x;
    const int warp = tid >> 5, lane = tid & 31;
    const int wm = (warp & 1) * 64;    // warp M offset
    const int wn = (warp >> 1) * 64;   // warp N offset
    const int g = lane >> 2, tg = lane & 3;

    float acc[4][8][4];
#pragma unroll
    for (int mi = 0; mi < 4; mi++)
#pragma unroll
        for (int ni = 0; ni < 8; ni++)
#pragma unroll
            for (int r = 0; r < 4; r++) acc[mi][ni][r] = 0.0f;

    // global load mapping: thread -> row lr (+64 strides), float4 at col lc4
    const int lr = tid >> 2;
    const int lc4 = (tid & 3) * 4;
    const int ro = lc4 >> 2;                  // offset within 4-float chunk
    const float* Ap = A + (size_t)(m0 + lr) * K_DIM + lc4;
    const float* Wp = W + (size_t)(ncol + lr) * K_DIM + lc4;
    const float* Pp = QKV ? (g_pe + ((m0 + lr) & (S_DIM - 1)) * C_DIM + lc4) : nullptr;
    // note: rows lr and lr+64 share the same PE row ((lr+64)&31 == lr&31)

    float4 ra[2], rb[4], rp;
    // prefetch kt = 0
    ra[0] = *(const float4*)(Ap);
    ra[1] = *(const float4*)(Ap + (size_t)64 * K_DIM);
    if (QKV) rp = *(const float4*)(Pp);
#pragma unroll
    for (int rr = 0; rr < 4; rr++)
        rb[rr] = *(const float4*)(Wp + (size_t)rr * 64 * K_DIM);

    for (int kt = 0; kt < NT; kt++) {
        float* Ab = As[kt & 1];
        float* Bb = Bs[kt & 1];

        // ---- store prefetched tile (tf32-rounded, permuted layout) ----
#pragma unroll
        for (int rr = 0; rr < 2; rr++) {
            int row = lr + rr * 64;
            float4 v = ra[rr];
            if (QKV) { v.x += rp.x; v.y += rp.y; v.z += rp.z; v.w += rp.w; }
            int base = row * 16 + ro;
            int s = (row & 3) << 2;
            Ab[base + ((0 << 2) ^ s)] = to_tf32(v.x);
            Ab[base + ((1 << 2) ^ s)] = to_tf32(v.y);
            Ab[base + ((2 << 2) ^ s)] = to_tf32(v.z);
            Ab[base + ((3 << 2) ^ s)] = to_tf32(v.w);
        }
#pragma unroll
        for (int rr = 0; rr < 4; rr++) {
            int row = lr + rr * 64;
            float4 v = rb[rr];
            int base = row * 16 + ro;
            int s = (row & 3) << 2;
            Bb[base + ((0 << 2) ^ s)] = to_tf32(v.x);
            Bb[base + ((1 << 2) ^ s)] = to_tf32(v.y);
            Bb[base + ((2 << 2) ^ s)] = to_tf32(v.z);
            Bb[base + ((3 << 2) ^ s)] = to_tf32(v.w);
        }
        __syncthreads();

        // ---- prefetch next tile ----
        if (kt + 1 < NT) {
            int k0 = (kt + 1) * BK;
            ra[0] = *(const float4*)(Ap + k0);
            ra[1] = *(const float4*)(Ap + (size_t)64 * K_DIM + k0);
            if (QKV) rp = *(const float4*)(Pp + k0);
#pragma unroll
            for (int rr = 0; rr < 4; rr++)
                rb[rr] = *(const float4*)(Wp + (size_t)rr * 64 * K_DIM + k0);
        }

        // ---- compute: 64 MMAs (4 mi x 8 ni x 2 ksteps) ----
        const int sw = (tg ^ (g & 3)) << 2;   // fragment chunk (row&3 == g&3 for all rows)
        float4 xa[4], ya[4];
#pragma unroll
        for (int mi = 0; mi < 4; mi++) {
            xa[mi] = *(const float4*)&Ab[(wm + mi * 16 + g) * 16 + sw];
            ya[mi] = *(const float4*)&Ab[(wm + mi * 16 + g + 8) * 16 + sw];
        }
#pragma unroll
        for (int h = 0; h < 2; h++) {
            float4 vb[4];
#pragma unroll
            for (int j = 0; j < 4; j++)
                vb[j] = *(const float4*)&Bb[(wn + (h * 4 + j) * 8 + g) * 16 + sw];
#pragma unroll
            for (int j = 0; j < 4; j++) {
                int ni = h * 4 + j;
#pragma unroll
                for (int mi = 0; mi < 4; mi++) {
                    // kstep 0: k = tg (x), tg+4 (y)
                    mma_tf32(acc[mi][ni], F2U(xa[mi].x), F2U(ya[mi].x),
                             F2U(xa[mi].y), F2U(ya[mi].y), F2U(vb[j].x), F2U(vb[j].y));
                    // kstep 1: k = tg+8 (z), tg+12 (w)
                    mma_tf32(acc[mi][ni], F2U(xa[mi].z), F2U(ya[mi].z),
                             F2U(xa[mi].w), F2U(ya[mi].w), F2U(vb[j].z), F2U(vb[j].w));
                }
            }
        }
        __syncthreads();
    }

    // ---- epilogue ----
#pragma unroll
    for (int mi = 0; mi < 4; mi++) {
#pragma unroll
        for (int ni = 0; ni < 8; ni++) {
            int row = m0 + wm + mi * 16 + g;
            int col = ncol + wn + ni * 8 + tg * 2;
            float b0v = 0.0f, b1v = 0.0f;
            if (!QKV) { b0v = bias[col]; b1v = bias[col + 1]; }
            float2 v01 = make_float2(acc[mi][ni][0] + b0v, acc[mi][ni][1] + b1v);
            float2 v23 = make_float2(acc[mi][ni][2] + b0v, acc[mi][ni][3] + b1v);
            *(float2*)(Cp + (size_t)row * C_DIM + col) = v01;
            *(float2*)(Cp + (size_t)(row + 8) * C_DIM + col) = v23;
        }
    }
}

// ---------------- attention: one CTA per (b, h) ----------------
constexpr int KSTR = 164;                       // floats per row (160 used)
constexpr int ATTN_SMEM = 3 * 32 * KSTR * 4;    // 62976 bytes

__global__ __launch_bounds__(256) void attn_kernel() {
    extern __shared__ float sm[];
    float* qs = sm;
    float* ks = sm + 32 * KSTR;
    float* vs = sm + 2 * 32 * KSTR;

    const int h = blockIdx.x;
    const int b = blockIdx.y;
    const int tid = threadIdx.x;
    const size_t base = (size_t)(b * S_DIM) * C_DIM + h * D_DIM;

    for (int t = tid; t < 3 * 32 * 40; t += 256) {
        int arr = t / 1280;
        int r = t - arr * 1280;
        int i = r / 40;
        int c4 = r - i * 40;
        float4 val = *(const float4*)(g_qkv + (size_t)arr * M_TOT * C_DIM + base +
                                      (size_t)i * C_DIM + c4 * 4);
        *(float4*)(sm + arr * (32 * KSTR) + i * KSTR + c4 * 4) = val;
    }
    __syncthreads();

    const int warp = tid >> 5, lane = tid & 31;
    const int i0 = warp * 4;

    float s0 = 0.f, s1 = 0.f, s2 = 0.f, s3 = 0.f;
    const float4* k4 = (const float4*)(ks + lane * KSTR);
    const float4* q0 = (const float4*)(qs + (i0 + 0) * KSTR);
    const float4* q1 = (const float4*)(qs + (i0 + 1) * KSTR);
    const float4* q2 = (const float4*)(qs + (i0 + 2) * KSTR);
    const float4* q3 = (const float4*)(qs + (i0 + 3) * KSTR);
#pragma unroll
    for (int c = 0; c < 40; c++) {
        float4 kv = k4[c];
        float4 a0 = q0[c], a1 = q1[c], a2 = q2[c], a3 = q3[c];
        s0 += a0.x * kv.x + a0.y * kv.y + a0.z * kv.z + a0.w * kv.w;
        s1 += a1.x * kv.x + a1.y * kv.y + a1.z * kv.z + a1.w * kv.w;
        s2 += a2.x * kv.x + a2.y * kv.y + a2.z * kv.z + a2.w * kv.w;
        s3 += a3.x * kv.x + a3.y * kv.y + a3.z * kv.z + a3.w * kv.w;
    }

    const float SCALE = 0.07905694150420949f;  // 1/sqrt(160)
    const unsigned FULL = 0xFFFFFFFFu;
    float p[4];
    float sv[4] = {s0 * SCALE, s1 * SCALE, s2 * SCALE, s3 * SCALE};
#pragma unroll
    for (int ii = 0; ii < 4; ii++) {
        float m = sv[ii];
#pragma unroll
        for (int o = 16; o > 0; o >>= 1) m = fmaxf(m, __shfl_xor_sync(FULL, m, o));
        float e = expf(sv[ii] - m);
        float sum = e;
#pragma unroll
        for (int o = 16; o > 0; o >>= 1) sum += __shfl_xor_sync(FULL, sum, o);
        p[ii] = e / sum;   // lane holds p[i0+ii][lane]
    }

    float4 oa[4], ob[4];
#pragma unroll
    for (int ii = 0; ii < 4; ii++) {
        oa[ii] = make_float4(0.f, 0.f, 0.f, 0.f);
        ob[ii] = make_float4(0.f, 0.f, 0.f, 0.f);
    }
    const bool has2 = (lane < 8);
#pragma unroll
    for (int j = 0; j < 32; j++) {
        const float4* v4 = (const float4*)(vs + j * KSTR);
        float4 vb = v4[lane];
        float4 vb2 = v4[has2 ? (lane + 32) : lane];
        float pj0 = __shfl_sync(FULL, p[0], j);
        float pj1 = __shfl_sync(FULL, p[1], j);
        float pj2 = __shfl_sync(FULL, p[2], j);
        float pj3 = __shfl_sync(FULL, p[3], j);
        oa[0].x += pj0 * vb.x; oa[0].y += pj0 * vb.y; oa[0].z += pj0 * vb.z; oa[0].w += pj0 * vb.w;
        oa[1].x += pj1 * vb.x; oa[1].y += pj1 * vb.y; oa[1].z += pj1 * vb.z; oa[1].w += pj1 * vb.w;
        oa[2].x += pj2 * vb.x; oa[2].y += pj2 * vb.y; oa[2].z += pj2 * vb.z; oa[2].w += pj2 * vb.w;
        oa[3].x += pj3 * vb.x; oa[3].y += pj3 * vb.y; oa[3].z += pj3 * vb.z; oa[3].w += pj3 * vb.w;
        ob[0].x += pj0 * vb2.x; ob[0].y += pj0 * vb2.y; ob[0].z += pj0 * vb2.z; ob[0].w += pj0 * vb2.w;
        ob[1].x += pj1 * vb2.x; ob[1].y += pj1 * vb2.y; ob[1].z += pj1 * vb2.z; ob[1].w += pj1 * vb2.w;
        ob[2].x += pj2 * vb2.x; ob[2].y += pj2 * vb2.y; ob[2].z += pj2 * vb2.z; ob[2].w += pj2 * vb2.w;
        ob[3].x += pj3 * vb2.x; ob[3].y += pj3 * vb2.y; ob[3].z += pj3 * vb2.z; ob[3].w += pj3 * vb2.w;
    }
#pragma unroll
    for (int ii = 0; ii < 4; ii++) {
        float* orow = g_attn + base + (size_t)(i0 + ii) * C_DIM;
        *(float4*)(orow + lane * 4) = oa[ii];
        if (has2) *(float4*)(orow + 128 + lane * 4) = ob[ii];
    }
}

// ---------------- launch ----------------
extern "C" void kernel_launch(void* const* d_in, const int* in_sizes, int n_in,
                              void* d_out, int out_size) {
    (void)in_sizes; (void)n_in; (void)out_size;
    const float* hidden = (const float*)d_in[0];
    const float* Wq = (const float*)d_in[1];
    const float* Wk = (const float*)d_in[2];
    const float* Wv = (const float*)d_in[3];
    const float* Wo = (const float*)d_in[4];
    const float* bo = (const float*)d_in[5];
    float* out = (float*)d_out;

    cudaFuncSetAttribute(attn_kernel, cudaFuncAttributeMaxDynamicSharedMemorySize, ATTN_SMEM);

    // 1) positional embedding table
    pe_kernel<<<(S_DIM * C_DIM + 255) / 256, 256>>>();

    // 2) fused QKV projection (pos-embed added on the fly)
    gemm_tf32_kernel<true><<<dim3(15, M_TOT / BM), 256>>>(hidden, Wq, Wk, Wv, nullptr, nullptr);

    // 3) attention per (b, h)
    attn_kernel<<<dim3(H_DIM, B_DIM), 256, ATTN_SMEM>>>();

    // 4) output projection + bias
    gemm_tf32_kernel<false><<<dim3(5, M_TOT / BM), 256>>>(g_attn /*unused*/, Wo, nullptr, nullptr, bo, out);
}